// round 7
// baseline (speedup 1.0000x reference)
#include <cuda_runtime.h>
#include <cuda_fp16.h>
#include <cstdint>

// ---------------------------------------------------------------------------
// HTSubTree restructured (fp16 storage, fp32 accumulation):
//   W01h[(o01*8+r02)][i01]             (512 x 64)   prep_w   (fp16)
//   W23[i23][(o23*8+r24)]              (64 x 512)   prep_w   (fp32 temp)
//   Vth[n=(o23*8+r04)][k=(r02*64+i23)] (512 x 512)  prep_v   (fp16, [n][k])
//   Th[b*64+o01][r02*64+i23] = W01h @ X_b           ht_k1m   (mma f16 k16)
//   out[b*64+o01][n]         = Th @ Vth^T           ht_k2m   (mma f16 k16)
// mma.sync m16n8k16 row.col: A[m][k] row-major, B stored [n][k] n-major.
// ---------------------------------------------------------------------------

__device__ __half g_W01h[512 * 64];
__device__ float  g_W23[64 * 512];
__device__ __half g_Vth[512 * 512];
__device__ __half g_Th[32768 * 512];

// ---------------- helpers --------------------------------------------------
__device__ __forceinline__ uint32_t smem_u32(const void* p) {
    uint32_t a;
    asm("{ .reg .u64 t; cvta.to.shared.u64 t, %1; cvt.u32.u64 %0, t; }" : "=r"(a) : "l"(p));
    return a;
}
__device__ __forceinline__ void cp16(uint32_t s, const void* g) {
    asm volatile("cp.async.cg.shared.global [%0], [%1], 16;" :: "r"(s), "l"(g) : "memory");
}
__device__ __forceinline__ void cp_commit() { asm volatile("cp.async.commit_group;" ::: "memory"); }
__device__ __forceinline__ void cp_wait0()  { asm volatile("cp.async.wait_group 0;" ::: "memory"); }
__device__ __forceinline__ void cp_wait1()  { asm volatile("cp.async.wait_group 1;" ::: "memory"); }

// fp16 mma, fp32 accumulate
__device__ __forceinline__ void mma16(float& d0, float& d1, float& d2, float& d3,
                                      uint32_t a0, uint32_t a1, uint32_t a2, uint32_t a3,
                                      uint32_t b0, uint32_t b1) {
    asm volatile(
        "mma.sync.aligned.m16n8k16.row.col.f32.f16.f16.f32 "
        "{%0,%1,%2,%3}, {%4,%5,%6,%7}, {%8,%9}, {%0,%1,%2,%3};"
        : "+f"(d0), "+f"(d1), "+f"(d2), "+f"(d3)
        : "r"(a0), "r"(a1), "r"(a2), "r"(a3), "r"(b0), "r"(b1));
}
__device__ __forceinline__ void ldsm4(uint32_t& r0, uint32_t& r1, uint32_t& r2,
                                      uint32_t& r3, uint32_t addr) {
    asm volatile("ldmatrix.sync.aligned.m8n8.x4.shared.b16 {%0,%1,%2,%3}, [%4];"
                 : "=r"(r0), "=r"(r1), "=r"(r2), "=r"(r3) : "r"(addr));
}

// ---------------------------------------------------------------------------
// prep_w: W01h (fp16) and W23 (fp32).
// factors [p][in][out][r] (512,64,8,1); cores: c0=C04, c1=C02, c2=C24
// ---------------------------------------------------------------------------
__global__ void prep_w(const float* __restrict__ factors,
                       const float* __restrict__ cores) {
    __shared__ float sf[2048];
    __shared__ float sc[1536];
    int tid = threadIdx.x;
    for (int i = tid; i < 2048; i += 256) sf[i] = factors[i];
    for (int i = tid; i < 1536; i += 256) sc[i] = cores[i];
    __syncthreads();

    int e = blockIdx.x * 256 + tid;
    if (e < 32768) {
        int row = e >> 6, i01 = e & 63;
        int o01 = row >> 3, r02 = row & 7;
        int o0 = o01 >> 3, o1 = o01 & 7, i0 = i01 >> 3, i1 = i01 & 7;
        const float* F0 = sf + i0 * 64 + o0 * 8;
        const float* F1 = sf + 512 + i1 * 64 + o1 * 8;
        const float* C02 = sc + 512;
        float acc = 0.f;
        #pragma unroll
        for (int r01 = 0; r01 < 8; ++r01) {
            float s = 0.f;
            #pragma unroll
            for (int r12 = 0; r12 < 8; ++r12)
                s += F1[r12] * C02[r01 * 64 + r12 * 8 + r02];
            acc += F0[r01] * s;
        }
        g_W01h[e] = __float2half_rn(acc);
    } else {
        int e2 = e - 32768;
        int i23 = e2 >> 9, rem = e2 & 511;
        int o23 = rem >> 3, r24 = rem & 7;
        int i2 = i23 >> 3, i3 = i23 & 7, o2 = o23 >> 3, o3 = o23 & 7;
        const float* F2 = sf + 1024 + i2 * 64 + o2 * 8;
        const float* F3 = sf + 1536 + i3 * 64 + o3 * 8;
        const float* C24 = sc + 1024;
        float acc = 0.f;
        #pragma unroll
        for (int r23 = 0; r23 < 8; ++r23) {
            float s = 0.f;
            #pragma unroll
            for (int r34 = 0; r34 < 8; ++r34)
                s += F3[r34] * C24[r23 * 64 + r34 * 8 + r24];
            acc += F2[r23] * s;
        }
        g_W23[e2] = acc;
    }
}

// prep_v: Vth[n][k] = sum_r24 W23[i23][(o23,r24)] C04[r02,r24,r04]  (fp16)
__global__ void prep_v(const float* __restrict__ cores) {
    __shared__ float sC04[512];
    int tid = threadIdx.x;
    for (int i = tid; i < 512; i += 256) sC04[i] = cores[i];
    __syncthreads();
    int g = blockIdx.x * 256 + tid;
    #pragma unroll
    for (int j = 0; j < 4; ++j) {
        int v = g + j * 65536;
        int kidx = v >> 9;          // r02*64 + i23
        int n    = v & 511;         // o23*8 + r04
        int r02 = kidx >> 6, i23 = kidx & 63;
        int o23 = n >> 3, r04 = n & 7;
        const float* w = g_W23 + i23 * 512 + o23 * 8;
        const float* c = sC04 + r02 * 64 + r04;
        float acc = 0.f;
        #pragma unroll
        for (int r24 = 0; r24 < 8; ++r24) acc += w[r24] * c[r24 * 8];
        g_Vth[(size_t)n * 512 + kidx] = __float2half_rn(acc);
    }
}

// ---------------------------------------------------------------------------
// ht_k1m: Th rows [mhalf*256,+256) for batch b = W01h-slice (256x64) @ X_b^T.
// grid (2, 512), 8 warps (4m x 2n), warp tile 64m x 32n, K=64 (4 k16-steps).
// SMEM (half): A[256][72], B[64][72]  (pad-8 rows -> conflict-free ldmatrix)
// ---------------------------------------------------------------------------
#define K1_AH   (256 * 72)                   // halves
#define K1_SMEM ((K1_AH + 64 * 72) * 2)      // 46080 bytes

__global__ __launch_bounds__(256, 2) void ht_k1m(const float* __restrict__ x) {
    extern __shared__ __half smh[];
    uint32_t sbase = smem_u32(smh);
    const int tid = threadIdx.x, wid = tid >> 5, lane = tid & 31;
    const int gid = lane >> 2, tig = lane & 3;
    const int wm = wid & 3, wn = wid >> 2;
    const int mhalf = blockIdx.x, b = blockIdx.y;

    // A = W01h rows [mhalf*256,+256): 128B/row via 8 cp16
    const __half* Ag = g_W01h + (size_t)(mhalf * 256) * 64;
    #pragma unroll
    for (int i = 0; i < 8; ++i) {
        int l = tid + i * 256;
        int row = l >> 3, s16 = (l & 7) * 8;          // halves
        cp16(sbase + (uint32_t)(row * 72 + s16) * 2, Ag + row * 64 + s16);
    }
    cp_commit();

    // B[n=i23][k=i01] = X_b^T, fp16. Each thread packs an i01-pair into half2.
    const float* xb = x + (size_t)b * 4096;
    __half* Bs = smh + K1_AH;
    #pragma unroll
    for (int i = 0; i < 8; ++i) {
        int l = tid + i * 256;
        int i23 = l & 63, i01p = (l >> 6) * 2;
        float v0 = __ldg(xb + i01p * 64 + i23);
        float v1 = __ldg(xb + (i01p + 1) * 64 + i23);
        *(__half2*)(Bs + i23 * 72 + i01p) = __floats2half2_rn(v0, v1);
    }
    cp_wait0();
    __syncthreads();

    // ldmatrix lane addressing (byte offsets)
    const uint32_t aoff = ((uint32_t)((wm * 64 + (lane & 7) + ((lane >> 3) & 1) * 8) * 72
                          + ((lane >> 4) & 1) * 8)) * 2;
    const uint32_t boff = (uint32_t)K1_AH * 2 +
                          ((uint32_t)((wn * 32 + (lane & 7) + ((lane >> 4) & 1) * 8) * 72
                          + ((lane >> 3) & 1) * 8)) * 2;

    float acc[4][4][4];
    #pragma unroll
    for (int mt = 0; mt < 4; ++mt)
        #pragma unroll
        for (int nt = 0; nt < 4; ++nt)
            #pragma unroll
            for (int q = 0; q < 4; ++q) acc[mt][nt][q] = 0.f;

    #pragma unroll
    for (int s = 0; s < 4; ++s) {
        const uint32_t kb = (uint32_t)(s * 16 * 2);     // 16 halves per step
        uint32_t a[4][4], bf[2][4];
        #pragma unroll
        for (int mt = 0; mt < 4; ++mt)
            ldsm4(a[mt][0], a[mt][1], a[mt][2], a[mt][3],
                  sbase + aoff + (uint32_t)(mt * 16 * 72 * 2) + kb);
        #pragma unroll
        for (int p = 0; p < 2; ++p)
            ldsm4(bf[p][0], bf[p][1], bf[p][2], bf[p][3],
                  sbase + boff + (uint32_t)(p * 16 * 72 * 2) + kb);
        #pragma unroll
        for (int mt = 0; mt < 4; ++mt)
            #pragma unroll
            for (int p = 0; p < 2; ++p) {
                mma16(acc[mt][2*p][0], acc[mt][2*p][1], acc[mt][2*p][2], acc[mt][2*p][3],
                      a[mt][0], a[mt][1], a[mt][2], a[mt][3], bf[p][0], bf[p][1]);
                mma16(acc[mt][2*p+1][0], acc[mt][2*p+1][1], acc[mt][2*p+1][2], acc[mt][2*p+1][3],
                      a[mt][0], a[mt][1], a[mt][2], a[mt][3], bf[p][2], bf[p][3]);
            }
    }

    // epilogue: fp16 pack, store to g_Th (flat (b*64+o01)*512 + r02*64+i23)
    __half* Tb = g_Th + (size_t)b * 32768;
    #pragma unroll
    for (int mt = 0; mt < 4; ++mt) {
        int r0 = mhalf * 256 + wm * 64 + mt * 16 + gid;
        #pragma unroll
        for (int nt = 0; nt < 4; ++nt) {
            int col = wn * 32 + nt * 8 + 2 * tig;
            *(__half2*)(Tb + (size_t)r0 * 64 + col) =
                __floats2half2_rn(acc[mt][nt][0], acc[mt][nt][1]);
            *(__half2*)(Tb + (size_t)(r0 + 8) * 64 + col) =
                __floats2half2_rn(acc[mt][nt][2], acc[mt][nt][3]);
        }
    }
}

// ---------------------------------------------------------------------------
// ht_k2m: out (32768x512 f32) = Th @ Vth^T.
// grid (4, 256), BM=128 BN=128 BK=32 (halves), 128 threads = 4 warps (2m x 2n),
// warp tile 64m x 64n, 3-stage cp.async, one __syncthreads per chunk.
// SMEM per stage (half): A[128][40] + B[128][40] = 20480 B; 3 stages = 60 KB.
// Per s-step (k16): 8 ldmatrix.x4 feed 32 independent HMMAs.
// ---------------------------------------------------------------------------
#define K2_AH    (128 * 40)                  // halves per matrix per stage
#define K2_STAGE (2 * K2_AH * 2)             // bytes per stage = 20480
#define K2_SMEM  (3 * K2_STAGE)              // 61440 bytes

__device__ __forceinline__ void k2_load(uint32_t sbase, int stage, int c,
                                        int mBase, int nBase, int tid) {
    const __half* Ag = g_Th  + (size_t)mBase * 512 + c * 32;
    const __half* Bg = g_Vth + (size_t)nBase * 512 + c * 32;
    uint32_t ab = sbase + (uint32_t)stage * K2_STAGE;
    uint32_t bb = ab + (uint32_t)K2_AH * 2;
    #pragma unroll
    for (int i = 0; i < 4; ++i) {
        int l = tid + i * 128;
        int row = l >> 2, s16 = (l & 3) * 8;          // halves
        cp16(ab + (uint32_t)(row * 40 + s16) * 2, Ag + (size_t)row * 512 + s16);
        cp16(bb + (uint32_t)(row * 40 + s16) * 2, Bg + (size_t)row * 512 + s16);
    }
    cp_commit();
}

__global__ __launch_bounds__(128, 2) void ht_k2m(float* __restrict__ C) {
    extern __shared__ __half smh[];
    uint32_t sbase = smem_u32(smh);
    const int tid = threadIdx.x, wid = tid >> 5, lane = tid & 31;
    const int gid = lane >> 2, tig = lane & 3;
    const int wm = wid & 1, wn = wid >> 1;
    const int mBase = blockIdx.y * 128, nBase = blockIdx.x * 128;

    // ldmatrix lane addressing (byte offsets within a stage)
    const uint32_t aoff = ((uint32_t)((wm * 64 + (lane & 7) + ((lane >> 3) & 1) * 8) * 40
                          + ((lane >> 4) & 1) * 8)) * 2;
    const uint32_t boff = (uint32_t)K2_AH * 2 +
                          ((uint32_t)((wn * 64 + (lane & 7) + ((lane >> 4) & 1) * 8) * 40
                          + ((lane >> 3) & 1) * 8)) * 2;

    float acc[4][8][4];
    #pragma unroll
    for (int mt = 0; mt < 4; ++mt)
        #pragma unroll
        for (int nt = 0; nt < 8; ++nt)
            #pragma unroll
            for (int q = 0; q < 4; ++q) acc[mt][nt][q] = 0.f;

    k2_load(sbase, 0, 0, mBase, nBase, tid);
    k2_load(sbase, 1, 1, mBase, nBase, tid);

    #pragma unroll 1
    for (int c = 0; c < 16; ++c) {
        if (c == 15) cp_wait0(); else cp_wait1();
        __syncthreads();
        // stage (c+2)%3 was consumed at iteration c-1 -> free
        if (c + 2 < 16) k2_load(sbase, (c + 2) % 3, c + 2, mBase, nBase, tid);

        const uint32_t stb = sbase + (uint32_t)(c % 3) * K2_STAGE;
        const uint32_t ab = stb + aoff;
        const uint32_t bb = stb + boff;
        #pragma unroll
        for (int s = 0; s < 2; ++s) {
            const uint32_t kb = (uint32_t)(s * 16 * 2);
            uint32_t a[4][4], bf[4][4];
            #pragma unroll
            for (int mt = 0; mt < 4; ++mt)
                ldsm4(a[mt][0], a[mt][1], a[mt][2], a[mt][3],
                      ab + kb + (uint32_t)(mt * 16 * 40 * 2));
            #pragma unroll
            for (int p = 0; p < 4; ++p)
                ldsm4(bf[p][0], bf[p][1], bf[p][2], bf[p][3],
                      bb + kb + (uint32_t)(p * 16 * 40 * 2));
            #pragma unroll
            for (int p = 0; p < 4; ++p) {
                #pragma unroll
                for (int mt = 0; mt < 4; ++mt) {
                    mma16(acc[mt][2*p][0], acc[mt][2*p][1], acc[mt][2*p][2], acc[mt][2*p][3],
                          a[mt][0], a[mt][1], a[mt][2], a[mt][3], bf[p][0], bf[p][1]);
                    mma16(acc[mt][2*p+1][0], acc[mt][2*p+1][1], acc[mt][2*p+1][2], acc[mt][2*p+1][3],
                          a[mt][0], a[mt][1], a[mt][2], a[mt][3], bf[p][2], bf[p][3]);
                }
            }
        }
    }

    // epilogue (fp32 out)
    #pragma unroll
    for (int mt = 0; mt < 4; ++mt) {
        int r0 = mBase + wm * 64 + mt * 16 + gid;
        #pragma unroll
        for (int nt = 0; nt < 8; ++nt) {
            int col = nBase + wn * 64 + nt * 8 + 2 * tig;
            *(float2*)(C + (size_t)r0 * 512 + col) =
                make_float2(acc[mt][nt][0], acc[mt][nt][1]);
            *(float2*)(C + (size_t)(r0 + 8) * 512 + col) =
                make_float2(acc[mt][nt][2], acc[mt][nt][3]);
        }
    }
}

// ---------------------------------------------------------------------------
extern "C" void kernel_launch(void* const* d_in, const int* in_sizes, int n_in,
                              void* d_out, int out_size) {
    (void)in_sizes; (void)n_in; (void)out_size;
    const float* x       = (const float*)d_in[0];
    const float* factors = (const float*)d_in[1];
    const float* cores   = (const float*)d_in[2];
    float* out = (float*)d_out;

    cudaFuncSetAttribute(ht_k1m, cudaFuncAttributeMaxDynamicSharedMemorySize, K1_SMEM);
    cudaFuncSetAttribute(ht_k2m, cudaFuncAttributeMaxDynamicSharedMemorySize, K2_SMEM);

    prep_w<<<256, 256>>>(factors, cores);
    prep_v<<<256, 256>>>(cores);
    ht_k1m<<<dim3(2, 512), 256, K1_SMEM>>>(x);
    ht_k2m<<<dim3(4, 256), 128, K2_SMEM>>>(out);
}

// round 8
// speedup vs baseline: 1.0723x; 1.0723x over previous
#include <cuda_runtime.h>
#include <cuda_fp16.h>
#include <cstdint>

// ---------------------------------------------------------------------------
// HTSubTree restructured (fp16 storage, fp32 accumulation):
//   W01h[(o01*8+r02)][i01]             (512 x 64)   prep_w   (fp16)
//   W23[i23][(o23*8+r24)]              (64 x 512)   prep_w   (fp32 temp)
//   Vth[n=(o23*8+r04)][k=(r02*64+i23)] (512 x 512)  prep_v   (fp16, [n][k])
//   Th[b*64+o01][r02*64+i23] = W01h @ X_b           ht_k1m   (mma f16 k16)
//   out[b*64+o01][n]         = Th @ Vth^T           ht_k2m   (mma f16 k16)
// mma.sync m16n8k16 row.col: A[m][k] row-major, B stored [n][k] n-major.
// ---------------------------------------------------------------------------

__device__ __half g_W01h[512 * 64];
__device__ float  g_W23[64 * 512];
__device__ __half g_Vth[512 * 512];
__device__ __half g_Th[32768 * 512];

// ---------------- helpers --------------------------------------------------
__device__ __forceinline__ uint32_t smem_u32(const void* p) {
    uint32_t a;
    asm("{ .reg .u64 t; cvta.to.shared.u64 t, %1; cvt.u32.u64 %0, t; }" : "=r"(a) : "l"(p));
    return a;
}
__device__ __forceinline__ void cp16(uint32_t s, const void* g) {
    asm volatile("cp.async.cg.shared.global [%0], [%1], 16;" :: "r"(s), "l"(g) : "memory");
}
__device__ __forceinline__ void cp_commit() { asm volatile("cp.async.commit_group;" ::: "memory"); }
__device__ __forceinline__ void cp_wait0()  { asm volatile("cp.async.wait_group 0;" ::: "memory"); }
__device__ __forceinline__ void cp_wait1()  { asm volatile("cp.async.wait_group 1;" ::: "memory"); }

// fp16 mma, fp32 accumulate
__device__ __forceinline__ void mma16(float& d0, float& d1, float& d2, float& d3,
                                      uint32_t a0, uint32_t a1, uint32_t a2, uint32_t a3,
                                      uint32_t b0, uint32_t b1) {
    asm volatile(
        "mma.sync.aligned.m16n8k16.row.col.f32.f16.f16.f32 "
        "{%0,%1,%2,%3}, {%4,%5,%6,%7}, {%8,%9}, {%0,%1,%2,%3};"
        : "+f"(d0), "+f"(d1), "+f"(d2), "+f"(d3)
        : "r"(a0), "r"(a1), "r"(a2), "r"(a3), "r"(b0), "r"(b1));
}
__device__ __forceinline__ void ldsm4(uint32_t& r0, uint32_t& r1, uint32_t& r2,
                                      uint32_t& r3, uint32_t addr) {
    asm volatile("ldmatrix.sync.aligned.m8n8.x4.shared.b16 {%0,%1,%2,%3}, [%4];"
                 : "=r"(r0), "=r"(r1), "=r"(r2), "=r"(r3) : "r"(addr));
}

// ---------------------------------------------------------------------------
// prep_w: W01h (fp16) and W23 (fp32).
// factors [p][in][out][r] (512,64,8,1); cores: c0=C04, c1=C02, c2=C24
// ---------------------------------------------------------------------------
__global__ void prep_w(const float* __restrict__ factors,
                       const float* __restrict__ cores) {
    __shared__ float sf[2048];
    __shared__ float sc[1536];
    int tid = threadIdx.x;
    for (int i = tid; i < 2048; i += 256) sf[i] = factors[i];
    for (int i = tid; i < 1536; i += 256) sc[i] = cores[i];
    __syncthreads();

    int e = blockIdx.x * 256 + tid;
    if (e < 32768) {
        int row = e >> 6, i01 = e & 63;
        int o01 = row >> 3, r02 = row & 7;
        int o0 = o01 >> 3, o1 = o01 & 7, i0 = i01 >> 3, i1 = i01 & 7;
        const float* F0 = sf + i0 * 64 + o0 * 8;
        const float* F1 = sf + 512 + i1 * 64 + o1 * 8;
        const float* C02 = sc + 512;
        float acc = 0.f;
        #pragma unroll
        for (int r01 = 0; r01 < 8; ++r01) {
            float s = 0.f;
            #pragma unroll
            for (int r12 = 0; r12 < 8; ++r12)
                s += F1[r12] * C02[r01 * 64 + r12 * 8 + r02];
            acc += F0[r01] * s;
        }
        g_W01h[e] = __float2half_rn(acc);
    } else {
        int e2 = e - 32768;
        int i23 = e2 >> 9, rem = e2 & 511;
        int o23 = rem >> 3, r24 = rem & 7;
        int i2 = i23 >> 3, i3 = i23 & 7, o2 = o23 >> 3, o3 = o23 & 7;
        const float* F2 = sf + 1024 + i2 * 64 + o2 * 8;
        const float* F3 = sf + 1536 + i3 * 64 + o3 * 8;
        const float* C24 = sc + 1024;
        float acc = 0.f;
        #pragma unroll
        for (int r23 = 0; r23 < 8; ++r23) {
            float s = 0.f;
            #pragma unroll
            for (int r34 = 0; r34 < 8; ++r34)
                s += F3[r34] * C24[r23 * 64 + r34 * 8 + r24];
            acc += F2[r23] * s;
        }
        g_W23[e2] = acc;
    }
}

// prep_v: Vth[n][k] = sum_r24 W23[i23][(o23,r24)] C04[r02,r24,r04]  (fp16)
__global__ void prep_v(const float* __restrict__ cores) {
    __shared__ float sC04[512];
    int tid = threadIdx.x;
    for (int i = tid; i < 512; i += 256) sC04[i] = cores[i];
    __syncthreads();
    int g = blockIdx.x * 256 + tid;
    #pragma unroll
    for (int j = 0; j < 4; ++j) {
        int v = g + j * 65536;
        int kidx = v >> 9;          // r02*64 + i23
        int n    = v & 511;         // o23*8 + r04
        int r02 = kidx >> 6, i23 = kidx & 63;
        int o23 = n >> 3, r04 = n & 7;
        const float* w = g_W23 + i23 * 512 + o23 * 8;
        const float* c = sC04 + r02 * 64 + r04;
        float acc = 0.f;
        #pragma unroll
        for (int r24 = 0; r24 < 8; ++r24) acc += w[r24] * c[r24 * 8];
        g_Vth[(size_t)n * 512 + kidx] = __float2half_rn(acc);
    }
}

// ---------------------------------------------------------------------------
// ht_k1m: batched-persistent. grid (2, 128), 256 thr = 8 warps (4m x 2n).
// CTA: load W01h slice [mhalf*256,+256) ONCE; loop 4 batches with
// double-buffered raw-X cp.async prefetch; convert to fp16-transposed B
// in-CTA; 4 k16 mma steps; store Th.
// SMEM: A half[256][72] (36864B) | Xraw float[2][4096] (32768B) |
//       Bs half[64][72] (9216B)  => 78848B total.
// ---------------------------------------------------------------------------
#define K1_XRAW_OFF 36864
#define K1_BS_OFF   (36864 + 32768)
#define K1_SMEM     (K1_BS_OFF + 64 * 72 * 2)

__global__ __launch_bounds__(256, 2) void ht_k1m(const float* __restrict__ x) {
    extern __shared__ char smc[];
    uint32_t sbase = smem_u32(smc);
    __half* Bs = (__half*)(smc + K1_BS_OFF);
    const float* Xraw = (const float*)(smc + K1_XRAW_OFF);
    const int tid = threadIdx.x, wid = tid >> 5, lane = tid & 31;
    const int gid = lane >> 2, tig = lane & 3;
    const int wm = wid & 3, wn = wid >> 2;
    const int mhalf = blockIdx.x;
    const int b0 = blockIdx.y * 4;

    // group 0: A slice + Xraw[0]
    const __half* Ag = g_W01h + (size_t)(mhalf * 256) * 64;
    #pragma unroll
    for (int i = 0; i < 8; ++i) {
        int l = tid + i * 256;
        int row = l >> 3, s16 = (l & 7) * 8;
        cp16(sbase + (uint32_t)(row * 72 + s16) * 2, Ag + row * 64 + s16);
    }
    {
        const float* xb = x + (size_t)b0 * 4096;
        #pragma unroll
        for (int i = 0; i < 4; ++i) {
            int l = tid + i * 256;
            cp16(sbase + K1_XRAW_OFF + (uint32_t)l * 16, xb + l * 4);
        }
    }
    cp_commit();
    // group 1: Xraw[1]
    {
        const float* xb = x + (size_t)(b0 + 1) * 4096;
        #pragma unroll
        for (int i = 0; i < 4; ++i) {
            int l = tid + i * 256;
            cp16(sbase + K1_XRAW_OFF + 16384 + (uint32_t)l * 16, xb + l * 4);
        }
    }
    cp_commit();

    // ldmatrix lane addressing (byte offsets)
    const uint32_t aoff = ((uint32_t)((wm * 64 + (lane & 7) + ((lane >> 3) & 1) * 8) * 72
                          + ((lane >> 4) & 1) * 8)) * 2;
    const uint32_t boff = (uint32_t)K1_BS_OFF +
                          ((uint32_t)((wn * 32 + (lane & 7) + ((lane >> 4) & 1) * 8) * 72
                          + ((lane >> 3) & 1) * 8)) * 2;

    #pragma unroll 1
    for (int ib = 0; ib < 4; ++ib) {
        const int buf = ib & 1;
        if (ib == 3) cp_wait0(); else cp_wait1();
        __syncthreads();   // Xraw[buf] ready; prior mma reads of Bs complete

        // convert Xraw[buf] -> Bs[n=i23][k=i01] fp16 (pairs along i01)
        const float* xr = Xraw + buf * 4096;
        #pragma unroll
        for (int i = 0; i < 8; ++i) {
            int l = tid + i * 256;
            int i23 = l & 63, i01p = (l >> 6) * 2;
            float v0 = xr[i01p * 64 + i23];
            float v1 = xr[(i01p + 1) * 64 + i23];
            *(__half2*)(Bs + i23 * 72 + i01p) = __floats2half2_rn(v0, v1);
        }
        // prefetch next Xraw into buf^1
        if (ib + 2 < 4) {
            const float* xb = x + (size_t)(b0 + ib + 2) * 4096;
            #pragma unroll
            for (int i = 0; i < 4; ++i) {
                int l = tid + i * 256;
                cp16(sbase + K1_XRAW_OFF + (uint32_t)(buf * 16384) + (uint32_t)l * 16,
                     xb + l * 4);
            }
        }
        cp_commit();       // keep group accounting uniform
        __syncthreads();   // Bs ready

        float acc[4][4][4];
        #pragma unroll
        for (int mt = 0; mt < 4; ++mt)
            #pragma unroll
            for (int nt = 0; nt < 4; ++nt)
                #pragma unroll
                for (int q = 0; q < 4; ++q) acc[mt][nt][q] = 0.f;

        #pragma unroll
        for (int s = 0; s < 4; ++s) {
            const uint32_t kb = (uint32_t)(s * 16 * 2);
            uint32_t a[4][4], bf[2][4];
            #pragma unroll
            for (int mt = 0; mt < 4; ++mt)
                ldsm4(a[mt][0], a[mt][1], a[mt][2], a[mt][3],
                      sbase + aoff + (uint32_t)(mt * 16 * 72 * 2) + kb);
            #pragma unroll
            for (int p = 0; p < 2; ++p)
                ldsm4(bf[p][0], bf[p][1], bf[p][2], bf[p][3],
                      sbase + boff + (uint32_t)(p * 16 * 72 * 2) + kb);
            #pragma unroll
            for (int mt = 0; mt < 4; ++mt)
                #pragma unroll
                for (int p = 0; p < 2; ++p) {
                    mma16(acc[mt][2*p][0], acc[mt][2*p][1], acc[mt][2*p][2], acc[mt][2*p][3],
                          a[mt][0], a[mt][1], a[mt][2], a[mt][3], bf[p][0], bf[p][1]);
                    mma16(acc[mt][2*p+1][0], acc[mt][2*p+1][1], acc[mt][2*p+1][2], acc[mt][2*p+1][3],
                          a[mt][0], a[mt][1], a[mt][2], a[mt][3], bf[p][2], bf[p][3]);
                }
        }

        // epilogue: fp16 pack, store to g_Th (flat (b*64+o01)*512 + r02*64+i23)
        __half* Tb = g_Th + (size_t)(b0 + ib) * 32768;
        #pragma unroll
        for (int mt = 0; mt < 4; ++mt) {
            int r0 = mhalf * 256 + wm * 64 + mt * 16 + gid;
            #pragma unroll
            for (int nt = 0; nt < 4; ++nt) {
                int col = wn * 32 + nt * 8 + 2 * tig;
                *(__half2*)(Tb + (size_t)r0 * 64 + col) =
                    __floats2half2_rn(acc[mt][nt][0], acc[mt][nt][1]);
                *(__half2*)(Tb + (size_t)(r0 + 8) * 64 + col) =
                    __floats2half2_rn(acc[mt][nt][2], acc[mt][nt][3]);
            }
        }
    }
}

// ---------------------------------------------------------------------------
// ht_k2m: out (32768x512 f32) = Th @ Vth^T.   [R6 proven config]
// grid (4, 256), BM=128 BN=128 BK=64 (halves), 8 warps (4m x 2n),
// warp tile 32m x 64n, 3-stage cp.async, one __syncthreads per chunk.
// SMEM per stage (half): A[128][72] + B[128][72] = 36864 B.
// ---------------------------------------------------------------------------
#define K2_AH    (128 * 72)                  // halves per matrix per stage
#define K2_STAGE (2 * K2_AH * 2)             // bytes per stage = 36864
#define K2_SMEM  (3 * K2_STAGE)              // 110592 bytes

__device__ __forceinline__ void k2_load(uint32_t sbase, int stage, int c,
                                        int mBase, int nBase, int tid) {
    const __half* Ag = g_Th  + (size_t)mBase * 512 + c * 64;
    const __half* Bg = g_Vth + (size_t)nBase * 512 + c * 64;
    uint32_t ab = sbase + (uint32_t)stage * K2_STAGE;
    uint32_t bb = ab + (uint32_t)K2_AH * 2;
    #pragma unroll
    for (int i = 0; i < 4; ++i) {
        int l = tid + i * 256;
        int row = l >> 3, s16 = (l & 7) * 8;          // halves
        cp16(ab + (uint32_t)(row * 72 + s16) * 2, Ag + (size_t)row * 512 + s16);
        cp16(bb + (uint32_t)(row * 72 + s16) * 2, Bg + (size_t)row * 512 + s16);
    }
    cp_commit();
}

__global__ __launch_bounds__(256, 2) void ht_k2m(float* __restrict__ C) {
    extern __shared__ __half smh[];
    uint32_t sbase = smem_u32(smh);
    const int tid = threadIdx.x, wid = tid >> 5, lane = tid & 31;
    const int gid = lane >> 2, tig = lane & 3;
    const int wm = wid & 3, wn = wid >> 2;
    const int mBase = blockIdx.y * 128, nBase = blockIdx.x * 128;

    // ldmatrix lane addressing (byte offsets within a stage)
    const uint32_t aoff = ((uint32_t)((wm * 32 + (lane & 7) + ((lane >> 3) & 1) * 8) * 72
                          + ((lane >> 4) & 1) * 8)) * 2;
    const uint32_t boff = (uint32_t)K2_AH * 2 +
                          ((uint32_t)((wn * 64 + (lane & 7) + ((lane >> 4) & 1) * 8) * 72
                          + ((lane >> 3) & 1) * 8)) * 2;

    float acc[2][8][4];
    #pragma unroll
    for (int mt = 0; mt < 2; ++mt)
        #pragma unroll
        for (int nt = 0; nt < 8; ++nt)
            #pragma unroll
            for (int q = 0; q < 4; ++q) acc[mt][nt][q] = 0.f;

    k2_load(sbase, 0, 0, mBase, nBase, tid);
    k2_load(sbase, 1, 1, mBase, nBase, tid);

    #pragma unroll 1
    for (int c = 0; c < 8; ++c) {
        if (c == 7) cp_wait0(); else cp_wait1();
        __syncthreads();
        // stage (c+2)%3 was consumed at iteration c-1 -> free
        if (c + 2 < 8) k2_load(sbase, (c + 2) % 3, c + 2, mBase, nBase, tid);

        const uint32_t stb = sbase + (uint32_t)(c % 3) * K2_STAGE;
        const uint32_t ab = stb + aoff;
        const uint32_t bb = stb + boff;
        #pragma unroll
        for (int s = 0; s < 4; ++s) {
            const uint32_t kb = (uint32_t)(s * 16 * 2);
            uint32_t a[2][4], bf[4][4];
            ldsm4(a[0][0], a[0][1], a[0][2], a[0][3], ab + kb);
            ldsm4(a[1][0], a[1][1], a[1][2], a[1][3], ab + kb + 16 * 72 * 2);
            #pragma unroll
            for (int p = 0; p < 4; ++p)
                ldsm4(bf[p][0], bf[p][1], bf[p][2], bf[p][3],
                      bb + kb + (uint32_t)(p * 16 * 72 * 2));
            #pragma unroll
            for (int p = 0; p < 4; ++p) {
                #pragma unroll
                for (int mt = 0; mt < 2; ++mt) {
                    mma16(acc[mt][2*p][0], acc[mt][2*p][1], acc[mt][2*p][2], acc[mt][2*p][3],
                          a[mt][0], a[mt][1], a[mt][2], a[mt][3], bf[p][0], bf[p][1]);
                    mma16(acc[mt][2*p+1][0], acc[mt][2*p+1][1], acc[mt][2*p+1][2], acc[mt][2*p+1][3],
                          a[mt][0], a[mt][1], a[mt][2], a[mt][3], bf[p][2], bf[p][3]);
                }
            }
        }
    }

    // epilogue (fp32 out)
    #pragma unroll
    for (int mt = 0; mt < 2; ++mt) {
        int r0 = mBase + wm * 32 + mt * 16 + gid;
        #pragma unroll
        for (int nt = 0; nt < 8; ++nt) {
            int col = nBase + wn * 64 + nt * 8 + 2 * tig;
            *(float2*)(C + (size_t)r0 * 512 + col) =
                make_float2(acc[mt][nt][0], acc[mt][nt][1]);
            *(float2*)(C + (size_t)(r0 + 8) * 512 + col) =
                make_float2(acc[mt][nt][2], acc[mt][nt][3]);
        }
    }
}

// ---------------------------------------------------------------------------
extern "C" void kernel_launch(void* const* d_in, const int* in_sizes, int n_in,
                              void* d_out, int out_size) {
    (void)in_sizes; (void)n_in; (void)out_size;
    const float* x       = (const float*)d_in[0];
    const float* factors = (const float*)d_in[1];
    const float* cores   = (const float*)d_in[2];
    float* out = (float*)d_out;

    cudaFuncSetAttribute(ht_k1m, cudaFuncAttributeMaxDynamicSharedMemorySize, K1_SMEM);
    cudaFuncSetAttribute(ht_k2m, cudaFuncAttributeMaxDynamicSharedMemorySize, K2_SMEM);

    prep_w<<<256, 256>>>(factors, cores);
    prep_v<<<256, 256>>>(cores);
    ht_k1m<<<dim3(2, 128), 256, K1_SMEM>>>(x);
    ht_k2m<<<dim3(4, 256), 256, K2_SMEM>>>(out);
}